// round 5
// baseline (speedup 1.0000x reference)
#include <cuda_runtime.h>
#include <math.h>

#define N_BOX     1048576
#define NUM_PTS   9
#define L_CONST   3.0f
#define EPS_F     1e-6f
#define GMM_EPS_F 1e-6f

#define BOX_PER_BLK 256
#define PRED_F4     (BOX_PER_BLK * 18 / 4)   // 1152
#define TARG_F4     (BOX_PER_BLK * 8 / 4)    // 512

__global__ void zero_out_kernel(float* out) {
    out[0] = 0.0f;
}

__global__ void __launch_bounds__(256) kld_loss_kernel(
    const float* __restrict__ pred,    // [N, 9, 2]
    const float* __restrict__ target,  // [N, 4, 2]
    float* __restrict__ out)
{
    __shared__ float4 s4[PRED_F4 + TARG_F4];   // 26624 B

    const int tid = threadIdx.x;

    // ---- coalesced staging: dense float4 streams ----
    const float4* gp = reinterpret_cast<const float4*>(pred)
                     + (size_t)blockIdx.x * PRED_F4;
    const float4* gt = reinterpret_cast<const float4*>(target)
                     + (size_t)blockIdx.x * TARG_F4;

    #pragma unroll
    for (int j = 0; j < 4; j++)
        s4[tid + j * 256] = gp[tid + j * 256];
    if (tid < PRED_F4 - 4 * 256)                  // remaining 128
        s4[tid + 4 * 256] = gp[tid + 4 * 256];
    #pragma unroll
    for (int j = 0; j < 2; j++)
        s4[PRED_F4 + tid + j * 256] = gt[tid + j * 256];

    __syncthreads();

    const float* s_pred = reinterpret_cast<const float*>(s4);            // [256][18]
    const float* s_targ = reinterpret_cast<const float*>(s4 + PRED_F4);  // [256][8]

    // ---- per-box math (read own row from smem) ----
    const float2* p2 = reinterpret_cast<const float2*>(s_pred + tid * 18);
    float px[NUM_PTS], py[NUM_PTS];
    #pragma unroll
    for (int k = 0; k < NUM_PTS; k++) {
        float2 v = p2[k];
        px[k] = v.x; py[k] = v.y;
    }

    const float4* t4 = reinterpret_cast<const float4*>(s_targ + tid * 8);
    float4 ta = t4[0];   // (t0x, t0y, t1x, t1y)
    float4 tb = t4[1];   // (t2x, t2y, t3x, t3y)

    // pred mean & covariance
    float sx = 0.f, sy = 0.f;
    #pragma unroll
    for (int k = 0; k < NUM_PTS; k++) { sx += px[k]; sy += py[k]; }
    const float inv_np = 1.0f / (float)NUM_PTS;
    float mux = sx * inv_np, muy = sy * inv_np;

    float cxx = 0.f, cxy = 0.f, cyy = 0.f;
    #pragma unroll
    for (int k = 0; k < NUM_PTS; k++) {
        float dx = px[k] - mux, dy = py[k] - muy;
        cxx += dx * dx; cxy += dx * dy; cyy += dy * dy;
    }
    cxx = cxx * inv_np + GMM_EPS_F;
    cxy = cxy * inv_np;
    cyy = cyy * inv_np + GMM_EPS_F;

    // target mean
    float tmux = (ta.x + ta.z + tb.x + tb.z) * 0.25f;
    float tmuy = (ta.y + ta.w + tb.y + tb.w) * 0.25f;

    // edges
    float e1x = ta.z - ta.x, e1y = ta.w - ta.y;   // t1 - t0
    float e2x = tb.x - ta.z, e2y = tb.y - ta.w;   // t2 - t1
    float w = e1x * e1x + e1y * e1y;
    float h = e2x * e2x + e2y * e2y;
    float inv_sw = rsqrtf(w);
    float c = e1x * inv_sw, s = e1y * inv_sw;

    const float dscale = 1.0f / (4.0f * L_CONST * L_CONST);
    float d0 = w * dscale, d1 = h * dscale;

    // t_var = R diag(d) R^T
    float c2 = c * c, s2 = s * s, cs = c * s;
    float t00 = c2 * d0 + s2 * d1;
    float t01 = cs * (d0 - d1);
    float t11 = s2 * d0 + c2 * d1;

    float t_det = t00 * t11 - t01 * t01;
    float p_det = cxx * cyy - cxy * cxy;

    float inv_tdet = 1.0f / t_det;
    float i00 =  t11 * inv_tdet;
    float i01 = -t01 * inv_tdet;
    float i11 =  t00 * inv_tdet;

    float dx = mux - tmux, dy = muy - tmuy;
    float term1 = dx * (i00 * dx + i01 * dy) + dy * (i01 * dx + i11 * dy);

    float trace = i00 * cxx + 2.0f * i01 * cxy + i11 * cyy;

    float term2 = trace + logf(t_det / p_det);
    float kld = 0.5f * (term1 + term2) - 1.0f;
    float kl_agg = fmaxf(kld, EPS_F);
    float loss = 1.0f - 1.0f / (2.0f + sqrtf(kl_agg));

    // ---- block reduction ----
    #pragma unroll
    for (int off = 16; off > 0; off >>= 1)
        loss += __shfl_down_sync(0xFFFFFFFFu, loss, off);

    __shared__ float warp_sums[8];
    int lane = tid & 31;
    int wid  = tid >> 5;
    if (lane == 0) warp_sums[wid] = loss;
    __syncthreads();

    if (wid == 0) {
        float v = (lane < 8) ? warp_sums[lane] : 0.0f;
        #pragma unroll
        for (int off = 4; off > 0; off >>= 1)
            v += __shfl_down_sync(0xFFFFFFFFu, v, off);
        if (lane == 0)
            atomicAdd(out, v * (1.0f / (float)N_BOX));
    }
}

extern "C" void kernel_launch(void* const* d_in, const int* in_sizes, int n_in,
                              void* d_out, int out_size) {
    const float* pred   = (const float*)d_in[0];
    const float* target = (const float*)d_in[1];
    float* out = (float*)d_out;

    zero_out_kernel<<<1, 1>>>(out);
    const int blocks = N_BOX / BOX_PER_BLK;   // 4096
    kld_loss_kernel<<<blocks, 256>>>(pred, target, out);
}

// round 6
// speedup vs baseline: 1.1379x; 1.1379x over previous
#include <cuda_runtime.h>
#include <math.h>

#define N_BOX     1048576
#define NUM_PTS   9
#define L_CONST   3.0f
#define EPS_F     1e-6f
#define GMM_EPS_F 1e-6f

__global__ void zero_out_kernel(float* out) {
    out[0] = 0.0f;
}

// Compute loss for one box given 18 pred floats and 8 target floats.
// Called with compile-time-constant base offsets into register arrays,
// fully unrolled -> everything stays in registers.
__device__ __forceinline__ float box_loss(const float* pf, const float* tf) {
    // pred mean
    float sx = 0.f, sy = 0.f;
    #pragma unroll
    for (int k = 0; k < NUM_PTS; k++) { sx += pf[2 * k]; sy += pf[2 * k + 1]; }
    const float inv_np = 1.0f / (float)NUM_PTS;
    float mux = sx * inv_np, muy = sy * inv_np;

    // pred covariance
    float cxx = 0.f, cxy = 0.f, cyy = 0.f;
    #pragma unroll
    for (int k = 0; k < NUM_PTS; k++) {
        float dx = pf[2 * k] - mux, dy = pf[2 * k + 1] - muy;
        cxx += dx * dx; cxy += dx * dy; cyy += dy * dy;
    }
    cxx = cxx * inv_np + GMM_EPS_F;
    cxy = cxy * inv_np;
    cyy = cyy * inv_np + GMM_EPS_F;

    // target corners: tf[0..7] = (t0x,t0y,t1x,t1y,t2x,t2y,t3x,t3y)
    float tmux = (tf[0] + tf[2] + tf[4] + tf[6]) * 0.25f;
    float tmuy = (tf[1] + tf[3] + tf[5] + tf[7]) * 0.25f;

    float e1x = tf[2] - tf[0], e1y = tf[3] - tf[1];
    float e2x = tf[4] - tf[2], e2y = tf[5] - tf[3];
    float w = e1x * e1x + e1y * e1y;
    float h = e2x * e2x + e2y * e2y;
    float inv_sw = rsqrtf(w);
    float c = e1x * inv_sw, s = e1y * inv_sw;

    const float dscale = 1.0f / (4.0f * L_CONST * L_CONST);
    float d0 = w * dscale, d1 = h * dscale;

    float c2 = c * c, s2 = s * s, cs = c * s;
    float t00 = c2 * d0 + s2 * d1;
    float t01 = cs * (d0 - d1);
    float t11 = s2 * d0 + c2 * d1;

    float t_det = t00 * t11 - t01 * t01;
    float p_det = cxx * cyy - cxy * cxy;

    float inv_tdet = 1.0f / t_det;
    float i00 =  t11 * inv_tdet;
    float i01 = -t01 * inv_tdet;
    float i11 =  t00 * inv_tdet;

    float dx = mux - tmux, dy = muy - tmuy;
    float term1 = dx * (i00 * dx + i01 * dy) + dy * (i01 * dx + i11 * dy);
    float trace = i00 * cxx + 2.0f * i01 * cxy + i11 * cyy;

    float term2 = trace + logf(t_det / p_det);
    float kld = 0.5f * (term1 + term2) - 1.0f;
    float kl_agg = fmaxf(kld, EPS_F);
    return 1.0f - 1.0f / (2.0f + sqrtf(kl_agg));
}

__global__ void __launch_bounds__(256) kld_loss_kernel(
    const float* __restrict__ pred,    // [N, 9, 2]
    const float* __restrict__ target,  // [N, 4, 2]
    float* __restrict__ out)
{
    const int gid = blockIdx.x * blockDim.x + threadIdx.x;   // box pair index

    // ---- load 2 boxes: 9 aligned float4 (pred) + 4 float4 (target) ----
    const float4* gp = reinterpret_cast<const float4*>(pred) + (size_t)gid * 9;
    const float4* gt = reinterpret_cast<const float4*>(target) + (size_t)gid * 4;

    float4 p4[9];
    float4 t4[4];
    #pragma unroll
    for (int j = 0; j < 9; j++) p4[j] = gp[j];
    #pragma unroll
    for (int j = 0; j < 4; j++) t4[j] = gt[j];

    // reinterpret as flat register arrays (constant indices after unroll)
    float pf[36], tf[16];
    #pragma unroll
    for (int j = 0; j < 9; j++) {
        pf[4 * j + 0] = p4[j].x; pf[4 * j + 1] = p4[j].y;
        pf[4 * j + 2] = p4[j].z; pf[4 * j + 3] = p4[j].w;
    }
    #pragma unroll
    for (int j = 0; j < 4; j++) {
        tf[4 * j + 0] = t4[j].x; tf[4 * j + 1] = t4[j].y;
        tf[4 * j + 2] = t4[j].z; tf[4 * j + 3] = t4[j].w;
    }

    float loss = box_loss(pf, tf) + box_loss(pf + 18, tf + 8);

    // ---- block reduction ----
    #pragma unroll
    for (int off = 16; off > 0; off >>= 1)
        loss += __shfl_down_sync(0xFFFFFFFFu, loss, off);

    __shared__ float warp_sums[8];
    int lane = threadIdx.x & 31;
    int wid  = threadIdx.x >> 5;
    if (lane == 0) warp_sums[wid] = loss;
    __syncthreads();

    if (wid == 0) {
        float v = (lane < 8) ? warp_sums[lane] : 0.0f;
        #pragma unroll
        for (int off = 4; off > 0; off >>= 1)
            v += __shfl_down_sync(0xFFFFFFFFu, v, off);
        if (lane == 0)
            atomicAdd(out, v * (1.0f / (float)N_BOX));
    }
}

extern "C" void kernel_launch(void* const* d_in, const int* in_sizes, int n_in,
                              void* d_out, int out_size) {
    const float* pred   = (const float*)d_in[0];
    const float* target = (const float*)d_in[1];
    float* out = (float*)d_out;

    zero_out_kernel<<<1, 1>>>(out);
    const int blocks = (N_BOX / 2) / 256;   // 2048
    kld_loss_kernel<<<blocks, 256>>>(pred, target, out);
}

// round 7
// speedup vs baseline: 1.2203x; 1.0724x over previous
#include <cuda_runtime.h>
#include <math.h>

#define N_BOX     1048576
#define NUM_PTS   9
#define L_CONST   3.0f
#define EPS_F     1e-6f
#define GMM_EPS_F 1e-6f

#define BOX_PER_CHUNK 256
#define PRED_F4   (BOX_PER_CHUNK * 18 / 4)   // 1152
#define TARG_F4   (BOX_PER_CHUNK * 8 / 4)    // 512
#define STAGE_F4  (PRED_F4 + TARG_F4)        // 1664
#define NSTAGE    2
#define GRID_BLKS 1024
#define CHUNKS_PER_BLK 4                     // 1024*4 = 4096 chunks = N_BOX/256

__global__ void zero_out_kernel(float* out) { out[0] = 0.0f; }

__device__ __forceinline__ void cp_async16(void* smem_ptr, const void* gptr) {
    unsigned saddr = (unsigned)__cvta_generic_to_shared(smem_ptr);
    asm volatile("cp.async.cg.shared.global [%0], [%1], 16;\n"
                 :: "r"(saddr), "l"(gptr));
}
__device__ __forceinline__ void cp_commit() {
    asm volatile("cp.async.commit_group;\n" ::: "memory");
}
template <int N>
__device__ __forceinline__ void cp_wait() {
    asm volatile("cp.async.wait_group %0;\n" :: "n"(N) : "memory");
}

__device__ __forceinline__ void issue_chunk(float4* st, const float4* gp,
                                            const float4* gt, int tid) {
    #pragma unroll
    for (int j = 0; j < 4; j++)
        cp_async16(&st[tid + j * 256], &gp[tid + j * 256]);
    if (tid < PRED_F4 - 4 * 256)
        cp_async16(&st[tid + 4 * 256], &gp[tid + 4 * 256]);
    #pragma unroll
    for (int j = 0; j < 2; j++)
        cp_async16(&st[PRED_F4 + tid + j * 256], &gt[tid + j * 256]);
    cp_commit();
}

__device__ __forceinline__ float box_loss(const float* s_pred, const float* s_targ,
                                          int tid) {
    const float2* p2 = reinterpret_cast<const float2*>(s_pred + tid * 18);
    float px[NUM_PTS], py[NUM_PTS];
    #pragma unroll
    for (int k = 0; k < NUM_PTS; k++) {
        float2 v = p2[k];
        px[k] = v.x; py[k] = v.y;
    }
    const float4* t4 = reinterpret_cast<const float4*>(s_targ + tid * 8);
    float4 ta = t4[0];
    float4 tb = t4[1];

    float sx = 0.f, sy = 0.f;
    #pragma unroll
    for (int k = 0; k < NUM_PTS; k++) { sx += px[k]; sy += py[k]; }
    const float inv_np = 1.0f / (float)NUM_PTS;
    float mux = sx * inv_np, muy = sy * inv_np;

    float cxx = 0.f, cxy = 0.f, cyy = 0.f;
    #pragma unroll
    for (int k = 0; k < NUM_PTS; k++) {
        float dx = px[k] - mux, dy = py[k] - muy;
        cxx += dx * dx; cxy += dx * dy; cyy += dy * dy;
    }
    cxx = cxx * inv_np + GMM_EPS_F;
    cxy = cxy * inv_np;
    cyy = cyy * inv_np + GMM_EPS_F;

    float tmux = (ta.x + ta.z + tb.x + tb.z) * 0.25f;
    float tmuy = (ta.y + ta.w + tb.y + tb.w) * 0.25f;

    float e1x = ta.z - ta.x, e1y = ta.w - ta.y;
    float e2x = tb.x - ta.z, e2y = tb.y - ta.w;
    float w = e1x * e1x + e1y * e1y;
    float h = e2x * e2x + e2y * e2y;
    float inv_sw = rsqrtf(w);
    float c = e1x * inv_sw, s = e1y * inv_sw;

    const float dscale = 1.0f / (4.0f * L_CONST * L_CONST);
    float d0 = w * dscale, d1 = h * dscale;

    float c2 = c * c, s2 = s * s, cs = c * s;
    float t00 = c2 * d0 + s2 * d1;
    float t01 = cs * (d0 - d1);
    float t11 = s2 * d0 + c2 * d1;

    float t_det = t00 * t11 - t01 * t01;
    float p_det = cxx * cyy - cxy * cxy;

    float inv_tdet = 1.0f / t_det;
    float i00 =  t11 * inv_tdet;
    float i01 = -t01 * inv_tdet;
    float i11 =  t00 * inv_tdet;

    float dx = mux - tmux, dy = muy - tmuy;
    float term1 = dx * (i00 * dx + i01 * dy) + dy * (i01 * dx + i11 * dy);
    float trace = i00 * cxx + 2.0f * i01 * cxy + i11 * cyy;

    float term2 = trace + logf(t_det / p_det);
    float kld = 0.5f * (term1 + term2) - 1.0f;
    float kl_agg = fmaxf(kld, EPS_F);
    return 1.0f - 1.0f / (2.0f + sqrtf(kl_agg));
}

__global__ void __launch_bounds__(256) kld_loss_kernel(
    const float* __restrict__ pred,
    const float* __restrict__ target,
    float* __restrict__ out)
{
    extern __shared__ float4 s4[];   // NSTAGE * STAGE_F4 float4 = 53248 B

    const int tid = threadIdx.x;
    const float4* gp_base = reinterpret_cast<const float4*>(pred);
    const float4* gt_base = reinterpret_cast<const float4*>(target);

    // chunk ids: blockIdx.x + i * GRID_BLKS,  i in [0, CHUNKS_PER_BLK)
    // prologue: issue chunk 0 into stage 0
    {
        int c0 = blockIdx.x;
        issue_chunk(s4, gp_base + (size_t)c0 * PRED_F4,
                        gt_base + (size_t)c0 * TARG_F4, tid);
    }

    float acc = 0.0f;

    #pragma unroll
    for (int i = 0; i < CHUNKS_PER_BLK; i++) {
        // issue next chunk into the other stage
        if (i + 1 < CHUNKS_PER_BLK) {
            int cn = blockIdx.x + (i + 1) * GRID_BLKS;
            float4* st = s4 + ((i + 1) & 1) * STAGE_F4;
            issue_chunk(st, gp_base + (size_t)cn * PRED_F4,
                            gt_base + (size_t)cn * TARG_F4, tid);
            cp_wait<1>();      // current chunk's group complete
        } else {
            cp_wait<0>();
        }
        __syncthreads();

        const float* stage = reinterpret_cast<const float*>(s4 + (i & 1) * STAGE_F4);
        acc += box_loss(stage, stage + PRED_F4 * 4, tid);

        __syncthreads();       // all reads done before this stage is overwritten
    }

    // ---- block reduction ----
    #pragma unroll
    for (int off = 16; off > 0; off >>= 1)
        acc += __shfl_down_sync(0xFFFFFFFFu, acc, off);

    __shared__ float warp_sums[8];
    int lane = tid & 31;
    int wid  = tid >> 5;
    if (lane == 0) warp_sums[wid] = acc;
    __syncthreads();

    if (wid == 0) {
        float v = (lane < 8) ? warp_sums[lane] : 0.0f;
        #pragma unroll
        for (int off = 4; off > 0; off >>= 1)
            v += __shfl_down_sync(0xFFFFFFFFu, v, off);
        if (lane == 0)
            atomicAdd(out, v * (1.0f / (float)N_BOX));
    }
}

extern "C" void kernel_launch(void* const* d_in, const int* in_sizes, int n_in,
                              void* d_out, int out_size) {
    const float* pred   = (const float*)d_in[0];
    const float* target = (const float*)d_in[1];
    float* out = (float*)d_out;

    static int configured = 0;
    if (!configured) {
        cudaFuncSetAttribute(kld_loss_kernel,
                             cudaFuncAttributeMaxDynamicSharedMemorySize,
                             NSTAGE * STAGE_F4 * sizeof(float4));
        configured = 1;
    }

    zero_out_kernel<<<1, 1>>>(out);
    kld_loss_kernel<<<GRID_BLKS, 256, NSTAGE * STAGE_F4 * sizeof(float4)>>>(
        pred, target, out);
}

// round 8
// speedup vs baseline: 1.3378x; 1.0963x over previous
#include <cuda_runtime.h>
#include <math.h>

#define N_BOX     1048576
#define NUM_PTS   9
#define L_CONST   3.0f
#define EPS_F     1e-6f
#define GMM_EPS_F 1e-6f

#define BOX_PER_CHUNK 256
#define PRED_F4   (BOX_PER_CHUNK * 18 / 4)   // 1152
#define TARG_F4   (BOX_PER_CHUNK * 8 / 4)    // 512
#define STAGE_F4  (PRED_F4 + TARG_F4)        // 1664
#define NSTAGE    2
#define NCHUNK    (N_BOX / BOX_PER_CHUNK)    // 4096
#define GRID_BLKS 592                        // 4 * 148 (persistent, single wave)

__global__ void zero_out_kernel(float* out) { out[0] = 0.0f; }

__device__ __forceinline__ void cp_async16(void* smem_ptr, const void* gptr) {
    unsigned saddr = (unsigned)__cvta_generic_to_shared(smem_ptr);
    asm volatile("cp.async.cg.shared.global [%0], [%1], 16;\n"
                 :: "r"(saddr), "l"(gptr));
}
__device__ __forceinline__ void cp_commit() {
    asm volatile("cp.async.commit_group;\n" ::: "memory");
}
template <int N>
__device__ __forceinline__ void cp_wait() {
    asm volatile("cp.async.wait_group %0;\n" :: "n"(N) : "memory");
}

__device__ __forceinline__ void issue_chunk(float4* st, const float4* gp,
                                            const float4* gt, int tid) {
    #pragma unroll
    for (int j = 0; j < 4; j++)
        cp_async16(&st[tid + j * 256], &gp[tid + j * 256]);
    if (tid < PRED_F4 - 4 * 256)
        cp_async16(&st[tid + 4 * 256], &gp[tid + 4 * 256]);
    #pragma unroll
    for (int j = 0; j < 2; j++)
        cp_async16(&st[PRED_F4 + tid + j * 256], &gt[tid + j * 256]);
    cp_commit();
}

__device__ __forceinline__ float box_loss(const float* s_pred, const float* s_targ,
                                          int tid) {
    const float2* p2 = reinterpret_cast<const float2*>(s_pred + tid * 18);
    float px[NUM_PTS], py[NUM_PTS];
    #pragma unroll
    for (int k = 0; k < NUM_PTS; k++) {
        float2 v = p2[k];
        px[k] = v.x; py[k] = v.y;
    }
    const float4* t4 = reinterpret_cast<const float4*>(s_targ + tid * 8);
    float4 ta = t4[0];
    float4 tb = t4[1];

    float sx = 0.f, sy = 0.f;
    #pragma unroll
    for (int k = 0; k < NUM_PTS; k++) { sx += px[k]; sy += py[k]; }
    const float inv_np = 1.0f / (float)NUM_PTS;
    float mux = sx * inv_np, muy = sy * inv_np;

    float cxx = 0.f, cxy = 0.f, cyy = 0.f;
    #pragma unroll
    for (int k = 0; k < NUM_PTS; k++) {
        float dx = px[k] - mux, dy = py[k] - muy;
        cxx += dx * dx; cxy += dx * dy; cyy += dy * dy;
    }
    cxx = cxx * inv_np + GMM_EPS_F;
    cxy = cxy * inv_np;
    cyy = cyy * inv_np + GMM_EPS_F;

    float tmux = (ta.x + ta.z + tb.x + tb.z) * 0.25f;
    float tmuy = (ta.y + ta.w + tb.y + tb.w) * 0.25f;

    float e1x = ta.z - ta.x, e1y = ta.w - ta.y;
    float e2x = tb.x - ta.z, e2y = tb.y - ta.w;
    float w = e1x * e1x + e1y * e1y;
    float h = e2x * e2x + e2y * e2y;
    float inv_sw = rsqrtf(w);
    float c = e1x * inv_sw, s = e1y * inv_sw;

    const float dscale = 1.0f / (4.0f * L_CONST * L_CONST);
    float d0 = w * dscale, d1 = h * dscale;

    float c2 = c * c, s2 = s * s, cs = c * s;
    float t00 = c2 * d0 + s2 * d1;
    float t01 = cs * (d0 - d1);
    float t11 = s2 * d0 + c2 * d1;

    float t_det = t00 * t11 - t01 * t01;
    float p_det = cxx * cyy - cxy * cxy;

    float inv_tdet = 1.0f / t_det;
    float i00 =  t11 * inv_tdet;
    float i01 = -t01 * inv_tdet;
    float i11 =  t00 * inv_tdet;

    float dx = mux - tmux, dy = muy - tmuy;
    float term1 = dx * (i00 * dx + i01 * dy) + dy * (i01 * dx + i11 * dy);
    float trace = i00 * cxx + 2.0f * i01 * cxy + i11 * cyy;

    float term2 = trace + logf(t_det / p_det);
    float kld = 0.5f * (term1 + term2) - 1.0f;
    float kl_agg = fmaxf(kld, EPS_F);
    return 1.0f - 1.0f / (2.0f + sqrtf(kl_agg));
}

__global__ void __launch_bounds__(256) kld_loss_kernel(
    const float* __restrict__ pred,
    const float* __restrict__ target,
    float* __restrict__ out)
{
    extern __shared__ float4 s4[];   // NSTAGE * STAGE_F4 float4 = 53248 B

    const int tid = threadIdx.x;
    const float4* gp_base = reinterpret_cast<const float4*>(pred);
    const float4* gt_base = reinterpret_cast<const float4*>(target);

    // persistent grid-stride over chunks, double-buffered
    int c    = blockIdx.x;
    int next = c + GRID_BLKS;
    int buf  = 0;

    issue_chunk(s4, gp_base + (size_t)c * PRED_F4,
                    gt_base + (size_t)c * TARG_F4, tid);

    float acc = 0.0f;

    while (c < NCHUNK) {
        if (next < NCHUNK) {
            issue_chunk(s4 + (buf ^ 1) * STAGE_F4,
                        gp_base + (size_t)next * PRED_F4,
                        gt_base + (size_t)next * TARG_F4, tid);
            cp_wait<1>();
        } else {
            cp_wait<0>();
        }
        __syncthreads();

        const float* stage = reinterpret_cast<const float*>(s4 + buf * STAGE_F4);
        acc += box_loss(stage, stage + PRED_F4 * 4, tid);

        __syncthreads();   // reads done before this stage is reused

        c = next;
        next += GRID_BLKS;
        buf ^= 1;
    }

    // ---- block reduction ----
    #pragma unroll
    for (int off = 16; off > 0; off >>= 1)
        acc += __shfl_down_sync(0xFFFFFFFFu, acc, off);

    __shared__ float warp_sums[8];
    int lane = tid & 31;
    int wid  = tid >> 5;
    if (lane == 0) warp_sums[wid] = acc;
    __syncthreads();

    if (wid == 0) {
        float v = (lane < 8) ? warp_sums[lane] : 0.0f;
        #pragma unroll
        for (int off = 4; off > 0; off >>= 1)
            v += __shfl_down_sync(0xFFFFFFFFu, v, off);
        if (lane == 0)
            atomicAdd(out, v * (1.0f / (float)N_BOX));
    }
}

extern "C" void kernel_launch(void* const* d_in, const int* in_sizes, int n_in,
                              void* d_out, int out_size) {
    const float* pred   = (const float*)d_in[0];
    const float* target = (const float*)d_in[1];
    float* out = (float*)d_out;

    static int configured = 0;
    if (!configured) {
        cudaFuncSetAttribute(kld_loss_kernel,
                             cudaFuncAttributeMaxDynamicSharedMemorySize,
                             NSTAGE * STAGE_F4 * sizeof(float4));
        configured = 1;
    }

    zero_out_kernel<<<1, 1>>>(out);
    kld_loss_kernel<<<GRID_BLKS, 256, NSTAGE * STAGE_F4 * sizeof(float4)>>>(
        pred, target, out);
}

// round 9
// speedup vs baseline: 1.3492x; 1.0085x over previous
#include <cuda_runtime.h>
#include <math.h>

#define N_BOX     1048576
#define NUM_PTS   9
#define L_CONST   3.0f
#define EPS_F     1e-6f
#define GMM_EPS_F 1e-6f

#define BOX_PER_WCHUNK 32
#define WPRED_F4   (BOX_PER_WCHUNK * 18 / 4)   // 144
#define WTARG_F4   (BOX_PER_WCHUNK * 8 / 4)    // 64
#define WSTAGE_F4  (WPRED_F4 + WTARG_F4)       // 208
#define NSTAGE     2
#define NWCHUNK    (N_BOX / BOX_PER_WCHUNK)    // 32768
#define GRID_BLKS  592                         // 4 * 148, persistent single wave
#define WARPS_PER_BLK 8
#define TOTAL_WARPS  (GRID_BLKS * WARPS_PER_BLK)   // 4736

__global__ void zero_out_kernel(float* out) { out[0] = 0.0f; }

__device__ __forceinline__ void cp_async16(void* smem_ptr, const void* gptr) {
    unsigned saddr = (unsigned)__cvta_generic_to_shared(smem_ptr);
    asm volatile("cp.async.cg.shared.global [%0], [%1], 16;\n"
                 :: "r"(saddr), "l"(gptr));
}
__device__ __forceinline__ void cp_commit() {
    asm volatile("cp.async.commit_group;\n" ::: "memory");
}
template <int N>
__device__ __forceinline__ void cp_wait() {
    asm volatile("cp.async.wait_group %0;\n" :: "n"(N) : "memory");
}

// Warp-cooperative staging of one 32-box chunk.
__device__ __forceinline__ void issue_wchunk(float4* st, const float4* gp,
                                             const float4* gt, int lane) {
    #pragma unroll
    for (int j = 0; j < 4; j++)
        cp_async16(&st[lane + 32 * j], &gp[lane + 32 * j]);
    if (lane < WPRED_F4 - 4 * 32)                       // remaining 16
        cp_async16(&st[lane + 128], &gp[lane + 128]);
    #pragma unroll
    for (int j = 0; j < 2; j++)
        cp_async16(&st[WPRED_F4 + lane + 32 * j], &gt[lane + 32 * j]);
    cp_commit();
}

__device__ __forceinline__ float box_loss(const float* s_pred, const float* s_targ,
                                          int lane) {
    const float2* p2 = reinterpret_cast<const float2*>(s_pred + lane * 18);
    float px[NUM_PTS], py[NUM_PTS];
    #pragma unroll
    for (int k = 0; k < NUM_PTS; k++) {
        float2 v = p2[k];
        px[k] = v.x; py[k] = v.y;
    }
    const float4* t4 = reinterpret_cast<const float4*>(s_targ + lane * 8);
    float4 ta = t4[0];
    float4 tb = t4[1];

    float sx = 0.f, sy = 0.f;
    #pragma unroll
    for (int k = 0; k < NUM_PTS; k++) { sx += px[k]; sy += py[k]; }
    const float inv_np = 1.0f / (float)NUM_PTS;
    float mux = sx * inv_np, muy = sy * inv_np;

    float cxx = 0.f, cxy = 0.f, cyy = 0.f;
    #pragma unroll
    for (int k = 0; k < NUM_PTS; k++) {
        float dx = px[k] - mux, dy = py[k] - muy;
        cxx += dx * dx; cxy += dx * dy; cyy += dy * dy;
    }
    cxx = cxx * inv_np + GMM_EPS_F;
    cxy = cxy * inv_np;
    cyy = cyy * inv_np + GMM_EPS_F;

    float tmux = (ta.x + ta.z + tb.x + tb.z) * 0.25f;
    float tmuy = (ta.y + ta.w + tb.y + tb.w) * 0.25f;

    float e1x = ta.z - ta.x, e1y = ta.w - ta.y;
    float e2x = tb.x - ta.z, e2y = tb.y - ta.w;
    float w = e1x * e1x + e1y * e1y;
    float h = e2x * e2x + e2y * e2y;
    float inv_sw = rsqrtf(w);
    float c = e1x * inv_sw, s = e1y * inv_sw;

    const float dscale = 1.0f / (4.0f * L_CONST * L_CONST);
    float d0 = w * dscale, d1 = h * dscale;

    float c2 = c * c, s2 = s * s, cs = c * s;
    float t00 = c2 * d0 + s2 * d1;
    float t01 = cs * (d0 - d1);
    float t11 = s2 * d0 + c2 * d1;

    float t_det = t00 * t11 - t01 * t01;
    float p_det = cxx * cyy - cxy * cxy;

    float inv_tdet = 1.0f / t_det;
    float i00 =  t11 * inv_tdet;
    float i01 = -t01 * inv_tdet;
    float i11 =  t00 * inv_tdet;

    float dx = mux - tmux, dy = muy - tmuy;
    float term1 = dx * (i00 * dx + i01 * dy) + dy * (i01 * dx + i11 * dy);
    float trace = i00 * cxx + 2.0f * i01 * cxy + i11 * cyy;

    float term2 = trace + logf(t_det / p_det);
    float kld = 0.5f * (term1 + term2) - 1.0f;
    float kl_agg = fmaxf(kld, EPS_F);
    return 1.0f - 1.0f / (2.0f + sqrtf(kl_agg));
}

__global__ void __launch_bounds__(256) kld_loss_kernel(
    const float* __restrict__ pred,
    const float* __restrict__ target,
    float* __restrict__ out)
{
    // per-warp double-buffered slabs: 8 warps * 2 stages * 208 float4 = 53248 B
    extern __shared__ float4 s4[];

    const int tid  = threadIdx.x;
    const int lane = tid & 31;
    const int wid  = tid >> 5;
    float4* wslab = s4 + wid * (NSTAGE * WSTAGE_F4);

    const float4* gp_base = reinterpret_cast<const float4*>(pred);
    const float4* gt_base = reinterpret_cast<const float4*>(target);

    // warp-autonomous grid stride over 32-box chunks
    int c    = blockIdx.x * WARPS_PER_BLK + wid;
    int next = c + TOTAL_WARPS;
    int buf  = 0;

    issue_wchunk(wslab, gp_base + (size_t)c * WPRED_F4,
                        gt_base + (size_t)c * WTARG_F4, lane);

    float acc = 0.0f;

    while (c < NWCHUNK) {
        if (next < NWCHUNK) {
            issue_wchunk(wslab + (buf ^ 1) * WSTAGE_F4,
                         gp_base + (size_t)next * WPRED_F4,
                         gt_base + (size_t)next * WTARG_F4, lane);
            cp_wait<1>();
        } else {
            cp_wait<0>();
        }
        __syncwarp();

        const float* stage = reinterpret_cast<const float*>(wslab + buf * WSTAGE_F4);
        acc += box_loss(stage, stage + WPRED_F4 * 4, lane);

        __syncwarp();   // all lanes done reading before this stage is reused

        c = next;
        next += TOTAL_WARPS;
        buf ^= 1;
    }

    // ---- block reduction (once, at the end) ----
    #pragma unroll
    for (int off = 16; off > 0; off >>= 1)
        acc += __shfl_down_sync(0xFFFFFFFFu, acc, off);

    __shared__ float warp_sums[WARPS_PER_BLK];
    if (lane == 0) warp_sums[wid] = acc;
    __syncthreads();

    if (wid == 0) {
        float v = (lane < WARPS_PER_BLK) ? warp_sums[lane] : 0.0f;
        #pragma unroll
        for (int off = 4; off > 0; off >>= 1)
            v += __shfl_down_sync(0xFFFFFFFFu, v, off);
        if (lane == 0)
            atomicAdd(out, v * (1.0f / (float)N_BOX));
    }
}

extern "C" void kernel_launch(void* const* d_in, const int* in_sizes, int n_in,
                              void* d_out, int out_size) {
    const float* pred   = (const float*)d_in[0];
    const float* target = (const float*)d_in[1];
    float* out = (float*)d_out;

    static int configured = 0;
    if (!configured) {
        cudaFuncSetAttribute(kld_loss_kernel,
                             cudaFuncAttributeMaxDynamicSharedMemorySize,
                             WARPS_PER_BLK * NSTAGE * WSTAGE_F4 * sizeof(float4));
        configured = 1;
    }

    zero_out_kernel<<<1, 1>>>(out);
    kld_loss_kernel<<<GRID_BLKS, 256,
                      WARPS_PER_BLK * NSTAGE * WSTAGE_F4 * sizeof(float4)>>>(
        pred, target, out);
}